// round 8
// baseline (speedup 1.0000x reference)
#include <cuda_runtime.h>
#include <cstdint>

// ---------------- problem constants ----------------
#define B_TOK  512
#define H_DIM  1024
#define I_DIM  1024
#define TWO_I  2048
#define N_EXP  32
#define TOPK   4
#define NPAIR  (B_TOK * TOPK)   // 2048

#define EPS_RMS   1e-5f
#define ALPHA_SG  1.702f
#define LIMIT_SG  7.0f

// ---------------- scratch (device globals; no allocations allowed) ----------
__device__ float d_t[B_TOK * H_DIM];        // normalized activations (2 MB)
__device__ float d_a[NPAIR * I_DIM];        // swiglu outputs per pair (8 MB)
__device__ float d_o[NPAIR * H_DIM];        // scaled expert outputs per pair (8 MB)
__device__ int   d_gidx[B_TOK * TOPK];
__device__ float d_gw[B_TOK * TOPK];
__device__ int   d_cnt[N_EXP];
__device__ int   d_offs[N_EXP];
__device__ int   d_rank[N_EXP * B_TOK];
__device__ int   d_kbuf[N_EXP * B_TOK];
__device__ int   d_ptok[NPAIR];
__device__ float d_pw[NPAIR];
__device__ int   d_pslot[B_TOK * TOPK];

// ====================================================================
// K1: RMSNorm + gate logits + top-4 + softmax.  One block per token.
// ====================================================================
__global__ __launch_bounds__(256)
void route_kernel(const float* __restrict__ x,
                  const float* __restrict__ nsc,
                  const float* __restrict__ gw,
                  const float* __restrict__ gb)
{
    const int b   = blockIdx.x;
    const int tid = threadIdx.x;     // 256

    __shared__ float ts[H_DIM];
    __shared__ float red[8];
    __shared__ float gsm[N_EXP];

    // load 4 contiguous x values
    float4 xv = reinterpret_cast<const float4*>(x)[b * 256 + tid];
    float ss = xv.x * xv.x + xv.y * xv.y + xv.z * xv.z + xv.w * xv.w;
    #pragma unroll
    for (int o = 16; o; o >>= 1) ss += __shfl_xor_sync(0xFFFFFFFFu, ss, o);
    if ((tid & 31) == 0) red[tid >> 5] = ss;
    __syncthreads();
    if (tid < 8) {
        float v = red[tid];
        #pragma unroll
        for (int o = 4; o; o >>= 1) v += __shfl_xor_sync(0xFFu, v, o);
        if (tid == 0) red[0] = v;
    }
    __syncthreads();

    float vme = red[0] * (1.0f / (float)H_DIM) + EPS_RMS;
    float inv = rsqrtf(vme);
    inv = inv * (1.5f - 0.5f * vme * inv * inv);   // Newton refine

    float4 sv = reinterpret_cast<const float4*>(nsc)[tid];
    float4 tv;
    tv.x = xv.x * inv * sv.x;
    tv.y = xv.y * inv * sv.y;
    tv.z = xv.z * inv * sv.z;
    tv.w = xv.w * inv * sv.w;
    ts[tid * 4 + 0] = tv.x;
    ts[tid * 4 + 1] = tv.y;
    ts[tid * 4 + 2] = tv.z;
    ts[tid * 4 + 3] = tv.w;
    reinterpret_cast<float4*>(d_t + (size_t)b * H_DIM)[tid] = tv;
    __syncthreads();

    // gate: warp w handles experts 4w..4w+3
    const int warp = tid >> 5, lane = tid & 31;
    #pragma unroll
    for (int ee = 0; ee < 4; ee++) {
        const int e = warp * 4 + ee;
        const float* wr = gw + (size_t)e * H_DIM;
        float s = 0.0f;
        #pragma unroll 8
        for (int h = lane; h < H_DIM; h += 32) s = fmaf(ts[h], wr[h], s);
        #pragma unroll
        for (int o = 16; o; o >>= 1) s += __shfl_xor_sync(0xFFFFFFFFu, s, o);
        if (lane == 0) gsm[e] = s + gb[e];
    }
    __syncthreads();

    if (tid == 0) {
        float sv4[TOPK]; int si[TOPK]; unsigned used = 0;
        #pragma unroll
        for (int k = 0; k < TOPK; k++) {
            float best = -1e30f; int bi = 0;
            for (int e = 0; e < N_EXP; e++)
                if (!((used >> e) & 1u) && gsm[e] > best) { best = gsm[e]; bi = e; }
            used |= 1u << bi; sv4[k] = best; si[k] = bi;
        }
        float mx = sv4[0];          // sorted descending
        float es[TOPK], sum = 0.0f;
        #pragma unroll
        for (int k = 0; k < TOPK; k++) { es[k] = expf(sv4[k] - mx); sum += es[k]; }
        float rs = 1.0f / sum;
        #pragma unroll
        for (int k = 0; k < TOPK; k++) {
            d_gidx[b * TOPK + k] = si[k];
            d_gw[b * TOPK + k]   = es[k] * rs;
        }
    }
}

// ====================================================================
// K2: per-expert deterministic ranking (block = expert, thread = token)
// ====================================================================
__global__ __launch_bounds__(B_TOK)
void count_rank_kernel()
{
    const int e = blockIdx.x;
    const int t = threadIdx.x;   // token, 512 threads

    int km = -1;
    #pragma unroll
    for (int k = 0; k < TOPK; k++)
        if (d_gidx[t * TOPK + k] == e) km = k;
    const int p = (km >= 0) ? 1 : 0;

    __shared__ int s[B_TOK];
    s[t] = p;
    __syncthreads();
    for (int off = 1; off < B_TOK; off <<= 1) {
        int v = 0;
        if (t >= off) v = s[t - off];
        __syncthreads();
        s[t] += v;
        __syncthreads();
    }
    d_rank[e * B_TOK + t] = s[t] - p;  // exclusive rank in token order
    d_kbuf[e * B_TOK + t] = km;
    if (t == B_TOK - 1) d_cnt[e] = s[t];
}

// K3: tiny serial exclusive scan over 32 expert counts
__global__ void offsets_kernel()
{
    if (threadIdx.x == 0) {
        int s = 0;
        for (int e = 0; e < N_EXP; e++) { d_offs[e] = s; s += d_cnt[e]; }
    }
}

// K4: fill permutation / slot maps
__global__ __launch_bounds__(B_TOK)
void fill_perm_kernel()
{
    const int e = blockIdx.x;
    const int t = threadIdx.x;
    const int km = d_kbuf[e * B_TOK + t];
    if (km < 0) return;
    const int slot = d_offs[e] + d_rank[e * B_TOK + t];
    d_ptok[slot] = t;
    d_pw[slot]   = d_gw[t * TOPK + km];
    d_pslot[t * TOPK + km] = slot;
}

// ====================================================================
// Grouped GEMM tiles: BM=32, BN=128, BK=16, 64 threads, 8x8 per thread
// ====================================================================
#define BM 32
#define BN 128
#define BK 16
#define AS_STRIDE 36    // padded: bank = (4k+m)%32, f4-aligned
#define BS_STRIDE 132   // padded: bank = (4k+n)%32, f4-aligned

// --------- GEMM1: h = t_gathered @ mlp1_w[e]^T + b1; fused swiglu -> d_a ----
__global__ __launch_bounds__(64)
void mlp1_kernel(const float* __restrict__ w1, const float* __restrict__ b1)
{
    const int e   = blockIdx.y;
    const int n_e = d_cnt[e];
    const int m0  = blockIdx.x * BM;         // M-tiles fastest -> L2 weight reuse
    if (m0 >= n_e) return;
    const int n0   = blockIdx.z * BN;        // over 2I = 2048
    const int base = d_offs[e];
    const int tid  = threadIdx.x;            // 64

    __shared__ __align__(16) float As[BK][AS_STRIDE];
    __shared__ __align__(16) float Bs[BK][BS_STRIDE];

    // A (gathered rows of d_t)
    const int a_m = tid & 31;
    const int a_k = (tid >> 5) * 8;
    const int row = m0 + a_m;
    const float* Ap = nullptr;
    if (row < n_e) Ap = d_t + (size_t)d_ptok[base + row] * H_DIM;

    // B: each thread streams rows (n0+tid) and (n0+tid+64), 16 k each
    const float* Bp0 = w1 + ((size_t)e * TWO_I + n0 + tid) * H_DIM;
    const float* Bp1 = Bp0 + (size_t)64 * H_DIM;

    float acc[8][8];
    #pragma unroll
    for (int i = 0; i < 8; i++)
        #pragma unroll
        for (int j = 0; j < 8; j++) acc[i][j] = 0.0f;

    const int rg = tid & 3;     // row group: rows rg*8 .. rg*8+7
    const int cg = tid >> 2;    // col group: cols cg*8 .. cg*8+7

    for (int k0 = 0; k0 < H_DIM; k0 += BK) {
        float4 a0 = make_float4(0,0,0,0), a1 = make_float4(0,0,0,0);
        if (Ap) {
            a0 = *reinterpret_cast<const float4*>(Ap + k0 + a_k);
            a1 = *reinterpret_cast<const float4*>(Ap + k0 + a_k + 4);
        }
        float4 b00 = *reinterpret_cast<const float4*>(Bp0 + k0);
        float4 b01 = *reinterpret_cast<const float4*>(Bp0 + k0 + 4);
        float4 b02 = *reinterpret_cast<const float4*>(Bp0 + k0 + 8);
        float4 b03 = *reinterpret_cast<const float4*>(Bp0 + k0 + 12);
        float4 b10 = *reinterpret_cast<const float4*>(Bp1 + k0);
        float4 b11 = *reinterpret_cast<const float4*>(Bp1 + k0 + 4);
        float4 b12 = *reinterpret_cast<const float4*>(Bp1 + k0 + 8);
        float4 b13 = *reinterpret_cast<const float4*>(Bp1 + k0 + 12);

        __syncthreads();
        As[a_k + 0][a_m] = a0.x; As[a_k + 1][a_m] = a0.y;
        As[a_k + 2][a_m] = a0.z; As[a_k + 3][a_m] = a0.w;
        As[a_k + 4][a_m] = a1.x; As[a_k + 5][a_m] = a1.y;
        As[a_k + 6][a_m] = a1.z; As[a_k + 7][a_m] = a1.w;
        Bs[ 0][tid] = b00.x; Bs[ 1][tid] = b00.y; Bs[ 2][tid] = b00.z; Bs[ 3][tid] = b00.w;
        Bs[ 4][tid] = b01.x; Bs[ 5][tid] = b01.y; Bs[ 6][tid] = b01.z; Bs[ 7][tid] = b01.w;
        Bs[ 8][tid] = b02.x; Bs[ 9][tid] = b02.y; Bs[10][tid] = b02.z; Bs[11][tid] = b02.w;
        Bs[12][tid] = b03.x; Bs[13][tid] = b03.y; Bs[14][tid] = b03.z; Bs[15][tid] = b03.w;
        Bs[ 0][64 + tid] = b10.x; Bs[ 1][64 + tid] = b10.y; Bs[ 2][64 + tid] = b10.z; Bs[ 3][64 + tid] = b10.w;
        Bs[ 4][64 + tid] = b11.x; Bs[ 5][64 + tid] = b11.y; Bs[ 6][64 + tid] = b11.z; Bs[ 7][64 + tid] = b11.w;
        Bs[ 8][64 + tid] = b12.x; Bs[ 9][64 + tid] = b12.y; Bs[10][64 + tid] = b12.z; Bs[11][64 + tid] = b12.w;
        Bs[12][64 + tid] = b13.x; Bs[13][64 + tid] = b13.y; Bs[14][64 + tid] = b13.z; Bs[15][64 + tid] = b13.w;
        __syncthreads();

        #pragma unroll
        for (int kk = 0; kk < BK; kk++) {
            float4 av0 = *reinterpret_cast<const float4*>(&As[kk][rg * 8]);
            float4 av1 = *reinterpret_cast<const float4*>(&As[kk][rg * 8 + 4]);
            float4 bv0 = *reinterpret_cast<const float4*>(&Bs[kk][cg * 8]);
            float4 bv1 = *reinterpret_cast<const float4*>(&Bs[kk][cg * 8 + 4]);
            float ar[8] = {av0.x, av0.y, av0.z, av0.w, av1.x, av1.y, av1.z, av1.w};
            float br[8] = {bv0.x, bv0.y, bv0.z, bv0.w, bv1.x, bv1.y, bv1.z, bv1.w};
            #pragma unroll
            for (int i = 0; i < 8; i++)
                #pragma unroll
                for (int j = 0; j < 8; j++)
                    acc[i][j] = fmaf(ar[i], br[j], acc[i][j]);
        }
    }

    // epilogue: bias + swiglu (even col = glu, odd col = linear)
    #pragma unroll
    for (int i = 0; i < 8; i++) {
        const int m = m0 + rg * 8 + i;
        if (m >= n_e) continue;
        const size_t arow = (size_t)(base + m) * I_DIM;
        #pragma unroll
        for (int j = 0; j < 8; j += 2) {
            const int c = n0 + cg * 8 + j;      // even
            float hg = acc[i][j]     + b1[(size_t)e * TWO_I + c];
            float hl = acc[i][j + 1] + b1[(size_t)e * TWO_I + c + 1];
            hg = fminf(hg, LIMIT_SG);
            hl = fminf(fmaxf(hl, -LIMIT_SG), LIMIT_SG);
            const float sig = 1.0f / (1.0f + expf(-ALPHA_SG * hg));
            d_a[arow + (c >> 1)] = hg * sig * (hl + 1.0f);
        }
    }
}

// --------- GEMM2: o = a @ mlp2_w[e]^T + b2, scaled by routing weight -> d_o -
__global__ __launch_bounds__(64)
void mlp2_kernel(const float* __restrict__ w2, const float* __restrict__ b2)
{
    const int e   = blockIdx.y;
    const int n_e = d_cnt[e];
    const int m0  = blockIdx.x * BM;
    if (m0 >= n_e) return;
    const int n0   = blockIdx.z * BN;        // over H = 1024
    const int base = d_offs[e];
    const int tid  = threadIdx.x;

    __shared__ __align__(16) float As[BK][AS_STRIDE];
    __shared__ __align__(16) float Bs[BK][BS_STRIDE];

    const int a_m = tid & 31;
    const int a_k = (tid >> 5) * 8;
    const int row = m0 + a_m;
    const float* Ap = nullptr;
    if (row < n_e) Ap = d_a + (size_t)(base + row) * I_DIM;

    const float* Bp0 = w2 + ((size_t)e * H_DIM + n0 + tid) * I_DIM;
    const float* Bp1 = Bp0 + (size_t)64 * I_DIM;

    float acc[8][8];
    #pragma unroll
    for (int i = 0; i < 8; i++)
        #pragma unroll
        for (int j = 0; j < 8; j++) acc[i][j] = 0.0f;

    const int rg = tid & 3;
    const int cg = tid >> 2;

    for (int k0 = 0; k0 < I_DIM; k0 += BK) {
        float4 a0 = make_float4(0,0,0,0), a1 = make_float4(0,0,0,0);
        if (Ap) {
            a0 = *reinterpret_cast<const float4*>(Ap + k0 + a_k);
            a1 = *reinterpret_cast<const float4*>(Ap + k0 + a_k + 4);
        }
        float4 b00 = *reinterpret_cast<const float4*>(Bp0 + k0);
        float4 b01 = *reinterpret_cast<const float4*>(Bp0 + k0 + 4);
        float4 b02 = *reinterpret_cast<const float4*>(Bp0 + k0 + 8);
        float4 b03 = *reinterpret_cast<const float4*>(Bp0 + k0 + 12);
        float4 b10 = *reinterpret_cast<const float4*>(Bp1 + k0);
        float4 b11 = *reinterpret_cast<const float4*>(Bp1 + k0 + 4);
        float4 b12 = *reinterpret_cast<const float4*>(Bp1 + k0 + 8);
        float4 b13 = *reinterpret_cast<const float4*>(Bp1 + k0 + 12);

        __syncthreads();
        As[a_k + 0][a_m] = a0.x; As[a_k + 1][a_m] = a0.y;
        As[a_k + 2][a_m] = a0.z; As[a_k + 3][a_m] = a0.w;
        As[a_k + 4][a_m] = a1.x; As[a_k + 5][a_m] = a1.y;
        As[a_k + 6][a_m] = a1.z; As[a_k + 7][a_m] = a1.w;
        Bs[ 0][tid] = b00.x; Bs[ 1][tid] = b00.y; Bs[ 2][tid] = b00.z; Bs[ 3][tid] = b00.w;
        Bs[ 4][tid] = b01.x; Bs[ 5][tid] = b01.y; Bs[ 6][tid] = b01.z; Bs[ 7][tid] = b01.w;
        Bs[ 8][tid] = b02.x; Bs[ 9][tid] = b02.y; Bs[10][tid] = b02.z; Bs[11][tid] = b02.w;
        Bs[12][tid] = b03.x; Bs[13][tid] = b03.y; Bs[14][tid] = b03.z; Bs[15][tid] = b03.w;
        Bs[ 0][64 + tid] = b10.x; Bs[ 1][64 + tid] = b10.y; Bs[ 2][64 + tid] = b10.z; Bs[ 3][64 + tid] = b10.w;
        Bs[ 4][64 + tid] = b11.x; Bs[ 5][64 + tid] = b11.y; Bs[ 6][64 + tid] = b11.z; Bs[ 7][64 + tid] = b11.w;
        Bs[ 8][64 + tid] = b12.x; Bs[ 9][64 + tid] = b12.y; Bs[10][64 + tid] = b12.z; Bs[11][64 + tid] = b12.w;
        Bs[12][64 + tid] = b13.x; Bs[13][64 + tid] = b13.y; Bs[14][64 + tid] = b13.z; Bs[15][64 + tid] = b13.w;
        __syncthreads();

        #pragma unroll
        for (int kk = 0; kk < BK; kk++) {
            float4 av0 = *reinterpret_cast<const float4*>(&As[kk][rg * 8]);
            float4 av1 = *reinterpret_cast<const float4*>(&As[kk][rg * 8 + 4]);
            float4 bv0 = *reinterpret_cast<const float4*>(&Bs[kk][cg * 8]);
            float4 bv1 = *reinterpret_cast<const float4*>(&Bs[kk][cg * 8 + 4]);
            float ar[8] = {av0.x, av0.y, av0.z, av0.w, av1.x, av1.y, av1.z, av1.w};
            float br[8] = {bv0.x, bv0.y, bv0.z, bv0.w, bv1.x, bv1.y, bv1.z, bv1.w};
            #pragma unroll
            for (int i = 0; i < 8; i++)
                #pragma unroll
                for (int j = 0; j < 8; j++)
                    acc[i][j] = fmaf(ar[i], br[j], acc[i][j]);
        }
    }

    #pragma unroll
    for (int i = 0; i < 8; i++) {
        const int m = m0 + rg * 8 + i;
        if (m >= n_e) continue;
        const float pw = d_pw[base + m];
        float* orow = d_o + (size_t)(base + m) * H_DIM;
        #pragma unroll
        for (int j = 0; j < 8; j++) {
            const int c = n0 + cg * 8 + j;
            orow[c] = (acc[i][j] + b2[(size_t)e * H_DIM + c]) * pw;
        }
    }
}

// ====================================================================
// K7: combine: out[b,h] = x[b,h] + sum_k d_o[slot(b,k), h]
// ====================================================================
__global__ __launch_bounds__(256)
void combine_kernel(const float* __restrict__ x, float* __restrict__ out)
{
    const int b   = blockIdx.x;
    const int tid = threadIdx.x;   // 256, float4 each
    float4 acc = reinterpret_cast<const float4*>(x)[b * 256 + tid];
    #pragma unroll
    for (int k = 0; k < TOPK; k++) {
        const int slot = d_pslot[b * TOPK + k];
        float4 ov = reinterpret_cast<const float4*>(d_o + (size_t)slot * H_DIM)[tid];
        acc.x += ov.x; acc.y += ov.y; acc.z += ov.z; acc.w += ov.w;
    }
    reinterpret_cast<float4*>(out)[b * 256 + tid] = acc;
}

// ====================================================================
extern "C" void kernel_launch(void* const* d_in, const int* in_sizes, int n_in,
                              void* d_out, int out_size)
{
    (void)in_sizes; (void)n_in; (void)out_size;
    const float* x   = (const float*)d_in[0];
    const float* nsc = (const float*)d_in[1];
    const float* gw  = (const float*)d_in[2];
    const float* gb  = (const float*)d_in[3];
    const float* w1  = (const float*)d_in[4];
    const float* b1  = (const float*)d_in[5];
    const float* w2  = (const float*)d_in[6];
    const float* b2  = (const float*)d_in[7];
    float* out = (float*)d_out;

    route_kernel<<<B_TOK, 256>>>(x, nsc, gw, gb);
    count_rank_kernel<<<N_EXP, B_TOK>>>();
    offsets_kernel<<<1, 32>>>();
    fill_perm_kernel<<<N_EXP, B_TOK>>>();

    // M-tiles in grid.x (fastest) so same-weight-tile blocks are schedule-adjacent
    dim3 g1(B_TOK / BM, N_EXP, TWO_I / BN);   // (16, 32, 16)
    mlp1_kernel<<<g1, 64>>>(w1, b1);
    dim3 g2(B_TOK / BM, N_EXP, H_DIM / BN);   // (16, 32, 8)
    mlp2_kernel<<<g2, 64>>>(w2, b2);

    combine_kernel<<<B_TOK, 256>>>(x, out);
}

// round 9
// speedup vs baseline: 3.5766x; 3.5766x over previous
#include <cuda_runtime.h>
#include <cstdint>

// ---------------- problem constants ----------------
#define B_TOK  512
#define H_DIM  1024
#define I_DIM  1024
#define TWO_I  2048
#define N_EXP  32
#define TOPK   4
#define NPAIR  (B_TOK * TOPK)   // 2048

#define EPS_RMS   1e-5f
#define ALPHA_SG  1.702f
#define LIMIT_SG  7.0f

// ---------------- scratch (device globals; no allocations allowed) ----------
__device__ float d_t[B_TOK * H_DIM];        // normalized activations (2 MB)
__device__ float d_a[NPAIR * I_DIM];        // swiglu outputs per pair (8 MB)
__device__ float d_o[NPAIR * H_DIM];        // scaled expert outputs per pair (8 MB)
__device__ int   d_gidx[B_TOK * TOPK];
__device__ float d_gw[B_TOK * TOPK];
__device__ int   d_cnt[N_EXP];
__device__ int   d_offs[N_EXP];
__device__ int   d_rank[N_EXP * B_TOK];
__device__ int   d_kbuf[N_EXP * B_TOK];
__device__ int   d_ptok[NPAIR];
__device__ float d_pw[NPAIR];
__device__ int   d_pslot[B_TOK * TOPK];

// ---------------- small PTX helpers ----------------
__device__ __forceinline__ uint32_t f2tf32(float x) {
    uint32_t r;
    asm("cvt.rna.tf32.f32 %0, %1;" : "=r"(r) : "f"(x));
    return r;
}

__device__ __forceinline__ void mma_tf32(float* c, const uint32_t* a, const uint32_t* b) {
    asm volatile(
        "mma.sync.aligned.m16n8k8.row.col.f32.tf32.tf32.f32 "
        "{%0,%1,%2,%3}, {%4,%5,%6,%7}, {%8,%9}, {%0,%1,%2,%3};\n"
        : "+f"(c[0]), "+f"(c[1]), "+f"(c[2]), "+f"(c[3])
        : "r"(a[0]), "r"(a[1]), "r"(a[2]), "r"(a[3]), "r"(b[0]), "r"(b[1]));
}

__device__ __forceinline__ void cp_async16(float* dst, const float* src, int bytes) {
    uint32_t s = (uint32_t)__cvta_generic_to_shared(dst);
    asm volatile("cp.async.cg.shared.global [%0], [%1], 16, %2;\n"
                 :: "r"(s), "l"(src), "r"(bytes) : "memory");
}
__device__ __forceinline__ void cp_commit() {
    asm volatile("cp.async.commit_group;\n" ::: "memory");
}

// ====================================================================
// K1: RMSNorm + gate logits + top-4 + softmax.  One block per token.
// ====================================================================
__global__ __launch_bounds__(256)
void route_kernel(const float* __restrict__ x,
                  const float* __restrict__ nsc,
                  const float* __restrict__ gw,
                  const float* __restrict__ gb)
{
    const int b   = blockIdx.x;
    const int tid = threadIdx.x;     // 256

    __shared__ float ts[H_DIM];
    __shared__ float red[8];
    __shared__ float gsm[N_EXP];

    float4 xv = reinterpret_cast<const float4*>(x)[b * 256 + tid];
    float ss = xv.x * xv.x + xv.y * xv.y + xv.z * xv.z + xv.w * xv.w;
    #pragma unroll
    for (int o = 16; o; o >>= 1) ss += __shfl_xor_sync(0xFFFFFFFFu, ss, o);
    if ((tid & 31) == 0) red[tid >> 5] = ss;
    __syncthreads();
    if (tid < 8) {
        float v = red[tid];
        #pragma unroll
        for (int o = 4; o; o >>= 1) v += __shfl_xor_sync(0xFFu, v, o);
        if (tid == 0) red[0] = v;
    }
    __syncthreads();

    float vme = red[0] * (1.0f / (float)H_DIM) + EPS_RMS;
    float inv = rsqrtf(vme);
    inv = inv * (1.5f - 0.5f * vme * inv * inv);   // Newton refine

    float4 sv = reinterpret_cast<const float4*>(nsc)[tid];
    float4 tv;
    tv.x = xv.x * inv * sv.x;
    tv.y = xv.y * inv * sv.y;
    tv.z = xv.z * inv * sv.z;
    tv.w = xv.w * inv * sv.w;
    ts[tid * 4 + 0] = tv.x;
    ts[tid * 4 + 1] = tv.y;
    ts[tid * 4 + 2] = tv.z;
    ts[tid * 4 + 3] = tv.w;
    reinterpret_cast<float4*>(d_t + (size_t)b * H_DIM)[tid] = tv;
    __syncthreads();

    const int warp = tid >> 5, lane = tid & 31;
    #pragma unroll
    for (int ee = 0; ee < 4; ee++) {
        const int e = warp * 4 + ee;
        const float* wr = gw + (size_t)e * H_DIM;
        float s = 0.0f;
        #pragma unroll 8
        for (int h = lane; h < H_DIM; h += 32) s = fmaf(ts[h], wr[h], s);
        #pragma unroll
        for (int o = 16; o; o >>= 1) s += __shfl_xor_sync(0xFFFFFFFFu, s, o);
        if (lane == 0) gsm[e] = s + gb[e];
    }
    __syncthreads();

    if (tid == 0) {
        float sv4[TOPK]; int si[TOPK]; unsigned used = 0;
        #pragma unroll
        for (int k = 0; k < TOPK; k++) {
            float best = -1e30f; int bi = 0;
            for (int e = 0; e < N_EXP; e++)
                if (!((used >> e) & 1u) && gsm[e] > best) { best = gsm[e]; bi = e; }
            used |= 1u << bi; sv4[k] = best; si[k] = bi;
        }
        float mx = sv4[0];
        float es[TOPK], sum = 0.0f;
        #pragma unroll
        for (int k = 0; k < TOPK; k++) { es[k] = expf(sv4[k] - mx); sum += es[k]; }
        float rs = 1.0f / sum;
        #pragma unroll
        for (int k = 0; k < TOPK; k++) {
            d_gidx[b * TOPK + k] = si[k];
            d_gw[b * TOPK + k]   = es[k] * rs;
        }
    }
}

// ====================================================================
// K2: per-expert deterministic ranking (block = expert, thread = token)
// ====================================================================
__global__ __launch_bounds__(B_TOK)
void count_rank_kernel()
{
    const int e = blockIdx.x;
    const int t = threadIdx.x;

    int km = -1;
    #pragma unroll
    for (int k = 0; k < TOPK; k++)
        if (d_gidx[t * TOPK + k] == e) km = k;
    const int p = (km >= 0) ? 1 : 0;

    __shared__ int s[B_TOK];
    s[t] = p;
    __syncthreads();
    for (int off = 1; off < B_TOK; off <<= 1) {
        int v = 0;
        if (t >= off) v = s[t - off];
        __syncthreads();
        s[t] += v;
        __syncthreads();
    }
    d_rank[e * B_TOK + t] = s[t] - p;
    d_kbuf[e * B_TOK + t] = km;
    if (t == B_TOK - 1) d_cnt[e] = s[t];
}

__global__ void offsets_kernel()
{
    if (threadIdx.x == 0) {
        int s = 0;
        for (int e = 0; e < N_EXP; e++) { d_offs[e] = s; s += d_cnt[e]; }
    }
}

__global__ __launch_bounds__(B_TOK)
void fill_perm_kernel()
{
    const int e = blockIdx.x;
    const int t = threadIdx.x;
    const int km = d_kbuf[e * B_TOK + t];
    if (km < 0) return;
    const int slot = d_offs[e] + d_rank[e * B_TOK + t];
    d_ptok[slot] = t;
    d_pw[slot]   = d_gw[t * TOPK + km];
    d_pslot[t * TOPK + km] = slot;
}

// ====================================================================
// Grouped tf32 tensor-core GEMM.
//   BM=64, BN=128, BK=16, 128 threads (4 warps).
//   Warp w computes rows [0,64) x cols [w*32, w*32+32): 4 x 4 m16n8k8 tiles.
//   Double-buffered cp.async (2 stages). Smem rows padded to 20 floats ->
//   fragment LDS provably conflict-free ((20m+k) mod 32 distinct per warp).
// ====================================================================
#define GBM 64
#define GBN 128
#define GBK 16
#define APAD 20

template<bool MLP1>
__global__ __launch_bounds__(128, 4)
void moe_gemm_kernel(const float* __restrict__ W, const float* __restrict__ bias)
{
    const int e   = blockIdx.y;
    const int n_e = d_cnt[e];
    const int m0  = blockIdx.x * GBM;
    if (m0 >= n_e) return;                 // uniform early-exit: no loads issued
    const int NB   = MLP1 ? TWO_I : H_DIM; // weight N dimension
    const int n0   = blockIdx.z * GBN;
    const int base = d_offs[e];
    const int tid  = threadIdx.x;
    const int warp = tid >> 5, lane = tid & 31;
    const int g    = lane >> 2, tg = lane & 3;

    __shared__ float As[2][GBM][APAD];
    __shared__ float Bs[2][GBN][APAD];

    // ---- global source pointers (16B chunks: row = tid>>2 (+32i), col4 = tid&3)
    const float* asrc[2]; int asz[2];
    #pragma unroll
    for (int i = 0; i < 2; i++) {
        const int m   = (tid >> 2) + 32 * i;
        const int row = m0 + m;
        const bool v  = row < n_e;
        const float* p;
        if (MLP1) p = v ? d_t + (size_t)d_ptok[base + row] * H_DIM : d_t;
        else      p = v ? d_a + (size_t)(base + row) * I_DIM       : d_a;
        asrc[i] = p + (tid & 3) * 4;
        asz[i]  = v ? 16 : 0;              // zero-fill padded rows
    }
    const float* bsrc = W + ((size_t)e * NB + n0 + (tid >> 2)) * 1024 + (tid & 3) * 4;

    float acc[4][4][4];
    #pragma unroll
    for (int a = 0; a < 4; a++)
        #pragma unroll
        for (int b = 0; b < 4; b++)
            #pragma unroll
            for (int c = 0; c < 4; c++) acc[a][b][c] = 0.0f;

    // ---- prologue: stage 0
    {
        #pragma unroll
        for (int i = 0; i < 2; i++)
            cp_async16(&As[0][(tid >> 2) + 32 * i][(tid & 3) * 4], asrc[i], asz[i]);
        #pragma unroll
        for (int i = 0; i < 4; i++)
            cp_async16(&Bs[0][(tid >> 2) + 32 * i][(tid & 3) * 4],
                       bsrc + (size_t)32 * i * 1024, 16);
        cp_commit();
    }

    const int NIT = 1024 / GBK;   // 64
    for (int it = 0; it < NIT; ++it) {
        const int buf = it & 1;
        if (it + 1 < NIT) {
            const int k0 = (it + 1) * GBK;
            #pragma unroll
            for (int i = 0; i < 2; i++)
                cp_async16(&As[buf ^ 1][(tid >> 2) + 32 * i][(tid & 3) * 4],
                           asrc[i] + k0, asz[i]);
            #pragma unroll
            for (int i = 0; i < 4; i++)
                cp_async16(&Bs[buf ^ 1][(tid >> 2) + 32 * i][(tid & 3) * 4],
                           bsrc + (size_t)32 * i * 1024 + k0, 16);
            cp_commit();
            asm volatile("cp.async.wait_group 1;\n" ::: "memory");
        } else {
            asm volatile("cp.async.wait_group 0;\n" ::: "memory");
        }
        __syncthreads();

        #pragma unroll
        for (int ks = 0; ks < 2; ks++) {
            const int kb = ks * 8;
            uint32_t af[4][4], bf[4][2];
            #pragma unroll
            for (int mt = 0; mt < 4; mt++) {
                af[mt][0] = f2tf32(As[buf][mt * 16 + g    ][kb + tg]);
                af[mt][1] = f2tf32(As[buf][mt * 16 + g + 8][kb + tg]);
                af[mt][2] = f2tf32(As[buf][mt * 16 + g    ][kb + tg + 4]);
                af[mt][3] = f2tf32(As[buf][mt * 16 + g + 8][kb + tg + 4]);
            }
            #pragma unroll
            for (int nt = 0; nt < 4; nt++) {
                bf[nt][0] = f2tf32(Bs[buf][warp * 32 + nt * 8 + g][kb + tg]);
                bf[nt][1] = f2tf32(Bs[buf][warp * 32 + nt * 8 + g][kb + tg + 4]);
            }
            #pragma unroll
            for (int mt = 0; mt < 4; mt++)
                #pragma unroll
                for (int nt = 0; nt < 4; nt++)
                    mma_tf32(acc[mt][nt], af[mt], bf[nt]);
        }
        __syncthreads();
    }

    // ---- epilogue
    if (MLP1) {
        #pragma unroll
        for (int mt = 0; mt < 4; mt++) {
            const int r0 = m0 + mt * 16 + g;
            const int r1 = r0 + 8;
            #pragma unroll
            for (int nt = 0; nt < 4; nt++) {
                const int c = n0 + warp * 32 + nt * 8 + tg * 2;   // even column
                const float bg = bias[(size_t)e * TWO_I + c];
                const float bl = bias[(size_t)e * TWO_I + c + 1];
                if (r0 < n_e) {
                    float hg = fminf(acc[mt][nt][0] + bg, LIMIT_SG);
                    float hl = fminf(fmaxf(acc[mt][nt][1] + bl, -LIMIT_SG), LIMIT_SG);
                    const float sig = 1.0f / (1.0f + expf(-ALPHA_SG * hg));
                    d_a[(size_t)(base + r0) * I_DIM + (c >> 1)] = hg * sig * (hl + 1.0f);
                }
                if (r1 < n_e) {
                    float hg = fminf(acc[mt][nt][2] + bg, LIMIT_SG);
                    float hl = fminf(fmaxf(acc[mt][nt][3] + bl, -LIMIT_SG), LIMIT_SG);
                    const float sig = 1.0f / (1.0f + expf(-ALPHA_SG * hg));
                    d_a[(size_t)(base + r1) * I_DIM + (c >> 1)] = hg * sig * (hl + 1.0f);
                }
            }
        }
    } else {
        #pragma unroll
        for (int mt = 0; mt < 4; mt++) {
            const int r0 = m0 + mt * 16 + g;
            const int r1 = r0 + 8;
            const float pw0 = (r0 < n_e) ? d_pw[base + r0] : 0.0f;
            const float pw1 = (r1 < n_e) ? d_pw[base + r1] : 0.0f;
            #pragma unroll
            for (int nt = 0; nt < 4; nt++) {
                const int c = n0 + warp * 32 + nt * 8 + tg * 2;
                const float b0 = bias[(size_t)e * H_DIM + c];
                const float b1 = bias[(size_t)e * H_DIM + c + 1];
                if (r0 < n_e) {
                    float* orow = d_o + (size_t)(base + r0) * H_DIM;
                    orow[c]     = (acc[mt][nt][0] + b0) * pw0;
                    orow[c + 1] = (acc[mt][nt][1] + b1) * pw0;
                }
                if (r1 < n_e) {
                    float* orow = d_o + (size_t)(base + r1) * H_DIM;
                    orow[c]     = (acc[mt][nt][2] + b0) * pw1;
                    orow[c + 1] = (acc[mt][nt][3] + b1) * pw1;
                }
            }
        }
    }
}

// ====================================================================
// K7: combine: out[b,h] = x[b,h] + sum_k d_o[slot(b,k), h]
// ====================================================================
__global__ __launch_bounds__(256)
void combine_kernel(const float* __restrict__ x, float* __restrict__ out)
{
    const int b   = blockIdx.x;
    const int tid = threadIdx.x;
    float4 acc = reinterpret_cast<const float4*>(x)[b * 256 + tid];
    #pragma unroll
    for (int k = 0; k < TOPK; k++) {
        const int slot = d_pslot[b * TOPK + k];
        float4 ov = reinterpret_cast<const float4*>(d_o + (size_t)slot * H_DIM)[tid];
        acc.x += ov.x; acc.y += ov.y; acc.z += ov.z; acc.w += ov.w;
    }
    reinterpret_cast<float4*>(out)[b * 256 + tid] = acc;
}

// ====================================================================
extern "C" void kernel_launch(void* const* d_in, const int* in_sizes, int n_in,
                              void* d_out, int out_size)
{
    (void)in_sizes; (void)n_in; (void)out_size;
    const float* x   = (const float*)d_in[0];
    const float* nsc = (const float*)d_in[1];
    const float* gw  = (const float*)d_in[2];
    const float* gb  = (const float*)d_in[3];
    const float* w1  = (const float*)d_in[4];
    const float* b1  = (const float*)d_in[5];
    const float* w2  = (const float*)d_in[6];
    const float* b2  = (const float*)d_in[7];
    float* out = (float*)d_out;

    route_kernel<<<B_TOK, 256>>>(x, nsc, gw, gb);
    count_rank_kernel<<<N_EXP, B_TOK>>>();
    offsets_kernel<<<1, 32>>>();
    fill_perm_kernel<<<N_EXP, B_TOK>>>();

    // M-tiles fastest in grid.x -> same-weight-tile blocks schedule-adjacent (L2 reuse)
    dim3 g1(B_TOK / GBM, N_EXP, TWO_I / GBN);   // (8, 32, 16)
    moe_gemm_kernel<true><<<g1, 128>>>(w1, b1);
    dim3 g2(B_TOK / GBM, N_EXP, H_DIM / GBN);   // (8, 32, 8)
    moe_gemm_kernel<false><<<g2, 128>>>(w2, b2);

    combine_kernel<<<B_TOK, 256>>>(x, out);
}

// round 10
// speedup vs baseline: 3.5888x; 1.0034x over previous
#include <cuda_runtime.h>
#include <cstdint>

// ---------------- problem constants ----------------
#define B_TOK  512
#define H_DIM  1024
#define I_DIM  1024
#define TWO_I  2048
#define N_EXP  32
#define TOPK   4
#define NPAIR  (B_TOK * TOPK)   // 2048

#define EPS_RMS   1e-5f
#define ALPHA_SG  1.702f
#define LIMIT_SG  7.0f

// ---------------- scratch (device globals; no allocations allowed) ----------
__device__ float d_t[B_TOK * H_DIM];        // normalized activations (2 MB)
__device__ float d_a[NPAIR * I_DIM];        // swiglu outputs per pair (8 MB)
__device__ float d_o[NPAIR * H_DIM];        // scaled expert outputs per pair (8 MB)
__device__ int   d_gidx[B_TOK * TOPK];
__device__ float d_gw[B_TOK * TOPK];
__device__ int   d_cnt[N_EXP];
__device__ int   d_offs[N_EXP];
__device__ int   d_rank[N_EXP * B_TOK];
__device__ int   d_kbuf[N_EXP * B_TOK];
__device__ int   d_ptok[NPAIR];
__device__ float d_pw[NPAIR];
__device__ int   d_pslot[B_TOK * TOPK];

// ---------------- small PTX helpers ----------------
__device__ __forceinline__ uint32_t f2tf32(float x) {
    uint32_t r;
    asm("cvt.rna.tf32.f32 %0, %1;" : "=r"(r) : "f"(x));
    return r;
}

__device__ __forceinline__ void mma_tf32(float* c, const uint32_t* a, const uint32_t* b) {
    asm volatile(
        "mma.sync.aligned.m16n8k8.row.col.f32.tf32.tf32.f32 "
        "{%0,%1,%2,%3}, {%4,%5,%6,%7}, {%8,%9}, {%0,%1,%2,%3};\n"
        : "+f"(c[0]), "+f"(c[1]), "+f"(c[2]), "+f"(c[3])
        : "r"(a[0]), "r"(a[1]), "r"(a[2]), "r"(a[3]), "r"(b[0]), "r"(b[1]));
}

__device__ __forceinline__ void cp_async16(float* dst, const float* src, int bytes) {
    uint32_t s = (uint32_t)__cvta_generic_to_shared(dst);
    asm volatile("cp.async.cg.shared.global [%0], [%1], 16, %2;\n"
                 :: "r"(s), "l"(src), "r"(bytes) : "memory");
}
__device__ __forceinline__ void cp_commit() {
    asm volatile("cp.async.commit_group;\n" ::: "memory");
}

// ====================================================================
// K1: RMSNorm + gate logits + top-4 + softmax.  One block per token.
// ====================================================================
__global__ __launch_bounds__(256)
void route_kernel(const float* __restrict__ x,
                  const float* __restrict__ nsc,
                  const float* __restrict__ gw,
                  const float* __restrict__ gb)
{
    const int b   = blockIdx.x;
    const int tid = threadIdx.x;     // 256

    __shared__ float ts[H_DIM];
    __shared__ float red[8];
    __shared__ float gsm[N_EXP];

    float4 xv = reinterpret_cast<const float4*>(x)[b * 256 + tid];
    float ss = xv.x * xv.x + xv.y * xv.y + xv.z * xv.z + xv.w * xv.w;
    #pragma unroll
    for (int o = 16; o; o >>= 1) ss += __shfl_xor_sync(0xFFFFFFFFu, ss, o);
    if ((tid & 31) == 0) red[tid >> 5] = ss;
    __syncthreads();
    if (tid < 8) {
        float v = red[tid];
        #pragma unroll
        for (int o = 4; o; o >>= 1) v += __shfl_xor_sync(0xFFu, v, o);
        if (tid == 0) red[0] = v;
    }
    __syncthreads();

    float vme = red[0] * (1.0f / (float)H_DIM) + EPS_RMS;
    float inv = rsqrtf(vme);
    inv = inv * (1.5f - 0.5f * vme * inv * inv);   // Newton refine

    float4 sv = reinterpret_cast<const float4*>(nsc)[tid];
    float4 tv;
    tv.x = xv.x * inv * sv.x;
    tv.y = xv.y * inv * sv.y;
    tv.z = xv.z * inv * sv.z;
    tv.w = xv.w * inv * sv.w;
    ts[tid * 4 + 0] = tv.x;
    ts[tid * 4 + 1] = tv.y;
    ts[tid * 4 + 2] = tv.z;
    ts[tid * 4 + 3] = tv.w;
    reinterpret_cast<float4*>(d_t + (size_t)b * H_DIM)[tid] = tv;
    __syncthreads();

    const int warp = tid >> 5, lane = tid & 31;
    #pragma unroll
    for (int ee = 0; ee < 4; ee++) {
        const int e = warp * 4 + ee;
        const float* wr = gw + (size_t)e * H_DIM;
        float s = 0.0f;
        #pragma unroll 8
        for (int h = lane; h < H_DIM; h += 32) s = fmaf(ts[h], wr[h], s);
        #pragma unroll
        for (int o = 16; o; o >>= 1) s += __shfl_xor_sync(0xFFFFFFFFu, s, o);
        if (lane == 0) gsm[e] = s + gb[e];
    }
    __syncthreads();

    if (tid == 0) {
        float sv4[TOPK]; int si[TOPK]; unsigned used = 0;
        #pragma unroll
        for (int k = 0; k < TOPK; k++) {
            float best = -1e30f; int bi = 0;
            for (int e = 0; e < N_EXP; e++)
                if (!((used >> e) & 1u) && gsm[e] > best) { best = gsm[e]; bi = e; }
            used |= 1u << bi; sv4[k] = best; si[k] = bi;
        }
        float mx = sv4[0];
        float es[TOPK], sum = 0.0f;
        #pragma unroll
        for (int k = 0; k < TOPK; k++) { es[k] = expf(sv4[k] - mx); sum += es[k]; }
        float rs = 1.0f / sum;
        #pragma unroll
        for (int k = 0; k < TOPK; k++) {
            d_gidx[b * TOPK + k] = si[k];
            d_gw[b * TOPK + k]   = es[k] * rs;
        }
    }
}

// ====================================================================
// K2: per-expert deterministic ranking (block = expert, thread = token)
// ====================================================================
__global__ __launch_bounds__(B_TOK)
void count_rank_kernel()
{
    const int e = blockIdx.x;
    const int t = threadIdx.x;

    int km = -1;
    #pragma unroll
    for (int k = 0; k < TOPK; k++)
        if (d_gidx[t * TOPK + k] == e) km = k;
    const int p = (km >= 0) ? 1 : 0;

    __shared__ int s[B_TOK];
    s[t] = p;
    __syncthreads();
    for (int off = 1; off < B_TOK; off <<= 1) {
        int v = 0;
        if (t >= off) v = s[t - off];
        __syncthreads();
        s[t] += v;
        __syncthreads();
    }
    d_rank[e * B_TOK + t] = s[t] - p;
    d_kbuf[e * B_TOK + t] = km;
    if (t == B_TOK - 1) d_cnt[e] = s[t];
}

__global__ void offsets_kernel()
{
    if (threadIdx.x == 0) {
        int s = 0;
        for (int e = 0; e < N_EXP; e++) { d_offs[e] = s; s += d_cnt[e]; }
    }
}

__global__ __launch_bounds__(B_TOK)
void fill_perm_kernel()
{
    const int e = blockIdx.x;
    const int t = threadIdx.x;
    const int km = d_kbuf[e * B_TOK + t];
    if (km < 0) return;
    const int slot = d_offs[e] + d_rank[e * B_TOK + t];
    d_ptok[slot] = t;
    d_pw[slot]   = d_gw[t * TOPK + km];
    d_pslot[t * TOPK + km] = slot;
}

// ====================================================================
// Grouped tf32 tensor-core GEMM.
//   BM=64, BN=128, BK=16, 128 threads (4 warps).
//   Warp w computes rows [0,64) x cols [w*32, w*32+32): 4 x 4 m16n8k8 tiles.
//   Double-buffered cp.async (2 stages). Smem rows padded to 20 floats ->
//   fragment LDS provably conflict-free ((20m+k) mod 32 distinct per warp).
// ====================================================================
#define GBM 64
#define GBN 128
#define GBK 16
#define APAD 20

template<bool MLP1>
__global__ __launch_bounds__(128, 4)
void moe_gemm_kernel(const float* __restrict__ W, const float* __restrict__ bias)
{
    const int e   = blockIdx.y;
    const int n_e = d_cnt[e];
    const int m0  = blockIdx.x * GBM;
    if (m0 >= n_e) return;                 // uniform early-exit: no loads issued
    const int NB   = MLP1 ? TWO_I : H_DIM; // weight N dimension
    const int n0   = blockIdx.z * GBN;
    const int base = d_offs[e];
    const int tid  = threadIdx.x;
    const int warp = tid >> 5, lane = tid & 31;
    const int g    = lane >> 2, tg = lane & 3;

    __shared__ float As[2][GBM][APAD];
    __shared__ float Bs[2][GBN][APAD];

    // ---- global source pointers (16B chunks: row = tid>>2 (+32i), col4 = tid&3)
    const float* asrc[2]; int asz[2];
    #pragma unroll
    for (int i = 0; i < 2; i++) {
        const int m   = (tid >> 2) + 32 * i;
        const int row = m0 + m;
        const bool v  = row < n_e;
        const float* p;
        if (MLP1) p = v ? d_t + (size_t)d_ptok[base + row] * H_DIM : d_t;
        else      p = v ? d_a + (size_t)(base + row) * I_DIM       : d_a;
        asrc[i] = p + (tid & 3) * 4;
        asz[i]  = v ? 16 : 0;              // zero-fill padded rows
    }
    const float* bsrc = W + ((size_t)e * NB + n0 + (tid >> 2)) * 1024 + (tid & 3) * 4;

    float acc[4][4][4];
    #pragma unroll
    for (int a = 0; a < 4; a++)
        #pragma unroll
        for (int b = 0; b < 4; b++)
            #pragma unroll
            for (int c = 0; c < 4; c++) acc[a][b][c] = 0.0f;

    // ---- prologue: stage 0
    {
        #pragma unroll
        for (int i = 0; i < 2; i++)
            cp_async16(&As[0][(tid >> 2) + 32 * i][(tid & 3) * 4], asrc[i], asz[i]);
        #pragma unroll
        for (int i = 0; i < 4; i++)
            cp_async16(&Bs[0][(tid >> 2) + 32 * i][(tid & 3) * 4],
                       bsrc + (size_t)32 * i * 1024, 16);
        cp_commit();
    }

    const int NIT = 1024 / GBK;   // 64
    for (int it = 0; it < NIT; ++it) {
        const int buf = it & 1;
        if (it + 1 < NIT) {
            const int k0 = (it + 1) * GBK;
            #pragma unroll
            for (int i = 0; i < 2; i++)
                cp_async16(&As[buf ^ 1][(tid >> 2) + 32 * i][(tid & 3) * 4],
                           asrc[i] + k0, asz[i]);
            #pragma unroll
            for (int i = 0; i < 4; i++)
                cp_async16(&Bs[buf ^ 1][(tid >> 2) + 32 * i][(tid & 3) * 4],
                           bsrc + (size_t)32 * i * 1024 + k0, 16);
            cp_commit();
            asm volatile("cp.async.wait_group 1;\n" ::: "memory");
        } else {
            asm volatile("cp.async.wait_group 0;\n" ::: "memory");
        }
        __syncthreads();

        #pragma unroll
        for (int ks = 0; ks < 2; ks++) {
            const int kb = ks * 8;
            uint32_t af[4][4], bf[4][2];
            #pragma unroll
            for (int mt = 0; mt < 4; mt++) {
                af[mt][0] = f2tf32(As[buf][mt * 16 + g    ][kb + tg]);
                af[mt][1] = f2tf32(As[buf][mt * 16 + g + 8][kb + tg]);
                af[mt][2] = f2tf32(As[buf][mt * 16 + g    ][kb + tg + 4]);
                af[mt][3] = f2tf32(As[buf][mt * 16 + g + 8][kb + tg + 4]);
            }
            #pragma unroll
            for (int nt = 0; nt < 4; nt++) {
                bf[nt][0] = f2tf32(Bs[buf][warp * 32 + nt * 8 + g][kb + tg]);
                bf[nt][1] = f2tf32(Bs[buf][warp * 32 + nt * 8 + g][kb + tg + 4]);
            }
            #pragma unroll
            for (int mt = 0; mt < 4; mt++)
                #pragma unroll
                for (int nt = 0; nt < 4; nt++)
                    mma_tf32(acc[mt][nt], af[mt], bf[nt]);
        }
        __syncthreads();
    }

    // ---- epilogue
    if (MLP1) {
        #pragma unroll
        for (int mt = 0; mt < 4; mt++) {
            const int r0 = m0 + mt * 16 + g;
            const int r1 = r0 + 8;
            #pragma unroll
            for (int nt = 0; nt < 4; nt++) {
                const int c = n0 + warp * 32 + nt * 8 + tg * 2;   // even column
                const float bg = bias[(size_t)e * TWO_I + c];
                const float bl = bias[(size_t)e * TWO_I + c + 1];
                if (r0 < n_e) {
                    float hg = fminf(acc[mt][nt][0] + bg, LIMIT_SG);
                    float hl = fminf(fmaxf(acc[mt][nt][1] + bl, -LIMIT_SG), LIMIT_SG);
                    const float sig = 1.0f / (1.0f + expf(-ALPHA_SG * hg));
                    d_a[(size_t)(base + r0) * I_DIM + (c >> 1)] = hg * sig * (hl + 1.0f);
                }
                if (r1 < n_e) {
                    float hg = fminf(acc[mt][nt][2] + bg, LIMIT_SG);
                    float hl = fminf(fmaxf(acc[mt][nt][3] + bl, -LIMIT_SG), LIMIT_SG);
                    const float sig = 1.0f / (1.0f + expf(-ALPHA_SG * hg));
                    d_a[(size_t)(base + r1) * I_DIM + (c >> 1)] = hg * sig * (hl + 1.0f);
                }
            }
        }
    } else {
        #pragma unroll
        for (int mt = 0; mt < 4; mt++) {
            const int r0 = m0 + mt * 16 + g;
            const int r1 = r0 + 8;
            const float pw0 = (r0 < n_e) ? d_pw[base + r0] : 0.0f;
            const float pw1 = (r1 < n_e) ? d_pw[base + r1] : 0.0f;
            #pragma unroll
            for (int nt = 0; nt < 4; nt++) {
                const int c = n0 + warp * 32 + nt * 8 + tg * 2;
                const float b0 = bias[(size_t)e * H_DIM + c];
                const float b1 = bias[(size_t)e * H_DIM + c + 1];
                if (r0 < n_e) {
                    float* orow = d_o + (size_t)(base + r0) * H_DIM;
                    orow[c]     = (acc[mt][nt][0] + b0) * pw0;
                    orow[c + 1] = (acc[mt][nt][1] + b1) * pw0;
                }
                if (r1 < n_e) {
                    float* orow = d_o + (size_t)(base + r1) * H_DIM;
                    orow[c]     = (acc[mt][nt][2] + b0) * pw1;
                    orow[c + 1] = (acc[mt][nt][3] + b1) * pw1;
                }
            }
        }
    }
}

// ====================================================================
// K7: combine: out[b,h] = x[b,h] + sum_k d_o[slot(b,k), h]
// ====================================================================
__global__ __launch_bounds__(256)
void combine_kernel(const float* __restrict__ x, float* __restrict__ out)
{
    const int b   = blockIdx.x;
    const int tid = threadIdx.x;
    float4 acc = reinterpret_cast<const float4*>(x)[b * 256 + tid];
    #pragma unroll
    for (int k = 0; k < TOPK; k++) {
        const int slot = d_pslot[b * TOPK + k];
        float4 ov = reinterpret_cast<const float4*>(d_o + (size_t)slot * H_DIM)[tid];
        acc.x += ov.x; acc.y += ov.y; acc.z += ov.z; acc.w += ov.w;
    }
    reinterpret_cast<float4*>(out)[b * 256 + tid] = acc;
}

// ====================================================================
extern "C" void kernel_launch(void* const* d_in, const int* in_sizes, int n_in,
                              void* d_out, int out_size)
{
    (void)in_sizes; (void)n_in; (void)out_size;
    const float* x   = (const float*)d_in[0];
    const float* nsc = (const float*)d_in[1];
    const float* gw  = (const float*)d_in[2];
    const float* gb  = (const float*)d_in[3];
    const float* w1  = (const float*)d_in[4];
    const float* b1  = (const float*)d_in[5];
    const float* w2  = (const float*)d_in[6];
    const float* b2  = (const float*)d_in[7];
    float* out = (float*)d_out;

    route_kernel<<<B_TOK, 256>>>(x, nsc, gw, gb);
    count_rank_kernel<<<N_EXP, B_TOK>>>();
    offsets_kernel<<<1, 32>>>();
    fill_perm_kernel<<<N_EXP, B_TOK>>>();

    // M-tiles fastest in grid.x -> same-weight-tile blocks schedule-adjacent (L2 reuse)
    dim3 g1(B_TOK / GBM, N_EXP, TWO_I / GBN);   // (8, 32, 16)
    moe_gemm_kernel<true><<<g1, 128>>>(w1, b1);
    dim3 g2(B_TOK / GBM, N_EXP, H_DIM / GBN);   // (8, 32, 8)
    moe_gemm_kernel<false><<<g2, 128>>>(w2, b2);

    combine_kernel<<<B_TOK, 256>>>(x, out);
}